// round 4
// baseline (speedup 1.0000x reference)
#include <cuda_runtime.h>
#include <cuda_bf16.h>
#include <cstdint>

// EdgeBlock: out[e,:] = W @ concat(edges[e], nodes[recv[e]], nodes[send[e]]) + b
// E=500000, NODE_D=EDGE_D=128, IN_D=384, W [128,384] row-major, out [E,128] f32.
// SIMT fp32x2 GEMM (tcgen05 rejected by harness PTX target compute_103).

using ull = unsigned long long;

__device__ __forceinline__ ull pack_dup(float x) {
    ull r;
    asm("mov.b64 %0, {%1, %1};" : "=l"(r) : "f"(x));
    return r;
}
__device__ __forceinline__ void ffma2(ull& d, ull a, ull b) {
    asm("fma.rn.f32x2 %0, %1, %2, %0;" : "+l"(d) : "l"(a), "l"(b));
}
__device__ __forceinline__ void unpack2(ull v, float& lo, float& hi) {
    asm("mov.b64 {%0, %1}, %2;" : "=f"(lo), "=f"(hi) : "l"(v));
}

#define TE      128           // edges per CTA tile
#define KC      32            // K per chunk
#define NCHUNK  12
#define THREADS 512
#define XS_STR  36            // floats per Xs row (32 + pad4), 144B: 16B-aligned

// dynamic smem layout (bytes)
#define XS_OFF(b) ((b) * TE * XS_STR * 4)                  // 2 x 18432
#define WS_OFF(b) (2 * TE * XS_STR * 4 + (b) * KC * 128 * 4) // 2 x 16384
#define RIDX_OFF  (2 * TE * XS_STR * 4 + 2 * KC * 128 * 4)   // 69632
#define SIDX_OFF  (RIDX_OFF + TE * 4)
#define SM_TOTAL  (SIDX_OFF + TE * 4)                        // 70656

// W pre-transposed: g_Wt[c][kk][o] = W[o][c*32+kk]  (12 x 32 x 128 floats)
__device__ float g_Wt[NCHUNK * KC * 128];

__global__ void prep_W_kernel(const float* __restrict__ W) {
    int i = blockIdx.x * blockDim.x + threadIdx.x;   // over dst
    if (i >= NCHUNK * KC * 128) return;
    int o  = i & 127;
    int kk = (i >> 7) & 31;
    int c  = i >> 12;
    g_Wt[i] = W[o * 384 + c * KC + kk];
}

__global__ void __launch_bounds__(THREADS, 1)
edgeblock_kernel(const float* __restrict__ nodes,
                 const float* __restrict__ edges,
                 const int* __restrict__ recv,
                 const int* __restrict__ send,
                 const float* __restrict__ bias,
                 float* __restrict__ out,
                 int E)
{
    extern __shared__ char smem[];
    const int t  = threadIdx.x;
    const int tx = t & 15;           // 16 out-groups of 8
    const int ty = t >> 4;           // 32 edge-groups of 4
    const int o_base = tx * 8;
    const int e_base = ty * 4;
    const int e0 = blockIdx.x * TE;

    int* Ridx = (int*)(smem + RIDX_OFF);
    int* Sidx = (int*)(smem + SIDX_OFF);
    if (t < TE) {
        int e = e0 + t;
        Ridx[t] = (e < E) ? recv[e] : 0;
        Sidx[t] = (e < E) ? send[e] : 0;
    }

    float bb[8];
#pragma unroll
    for (int j = 0; j < 8; ++j) bb[j] = __ldg(&bias[o_base + j]);

    ull acc[4][4];
#pragma unroll
    for (int i = 0; i < 4; ++i)
#pragma unroll
        for (int j = 0; j < 4; ++j) acc[i][j] = 0ULL;

    // staging registers (2 float4 X + 2 float4 W per thread per chunk)
    const int sr = t >> 3;           // X stage row   (0..63)  [2 iters: +64]
    const int sq = t & 7;            // float4-in-row (0..7)
    float4 xst[2], wst[2];

    __syncthreads();                 // indices visible

    // ---- LDG for a chunk (into regs) ----
    auto ldg_chunk = [&](int c) {
        const int coff = (c & 3) * KC;
#pragma unroll
        for (int i = 0; i < 2; ++i) {
            int r = sr + i * 64;
            const float* src;
            if (c < 4) {
                int e = e0 + r;
                src = (e < E) ? edges + (size_t)e * 128 + coff : nullptr;
            } else if (c < 8) {
                src = nodes + (size_t)Ridx[r] * 128 + coff;
            } else {
                src = nodes + (size_t)Sidx[r] * 128 + coff;
            }
            xst[i] = src ? *reinterpret_cast<const float4*>(src + sq * 4)
                         : make_float4(0.f, 0.f, 0.f, 0.f);
        }
        const float4* wg = reinterpret_cast<const float4*>(g_Wt + c * (KC * 128));
#pragma unroll
        for (int i = 0; i < 2; ++i) wst[i] = wg[t + i * THREADS];
    };
    // ---- STS of staged regs into buffer b ----
    auto sts_chunk = [&](int b) {
        float* Xs = (float*)(smem + XS_OFF(b));
        float* Ws = (float*)(smem + WS_OFF(b));
#pragma unroll
        for (int i = 0; i < 2; ++i) {
            int r = sr + i * 64;
            *reinterpret_cast<float4*>(Xs + r * XS_STR + sq * 4) = xst[i];
        }
        float4* wsh = reinterpret_cast<float4*>(Ws);
#pragma unroll
        for (int i = 0; i < 2; ++i) wsh[t + i * THREADS] = wst[i];
    };

    // prologue
    ldg_chunk(0);
    sts_chunk(0);
    __syncthreads();

    for (int c = 0; c < NCHUNK; ++c) {
        if (c + 1 < NCHUNK) ldg_chunk(c + 1);

        const float* Xs = (const float*)(smem + XS_OFF(c & 1));
        const float* Ws = (const float*)(smem + WS_OFF(c & 1));

#pragma unroll
        for (int kk0 = 0; kk0 < KC; kk0 += 4) {
            float4 xr[4];
#pragma unroll
            for (int i = 0; i < 4; ++i)
                xr[i] = *reinterpret_cast<const float4*>(Xs + (e_base + i) * XS_STR + kk0);
#pragma unroll
            for (int kk = 0; kk < 4; ++kk) {
                const ulonglong2* wp =
                    reinterpret_cast<const ulonglong2*>(Ws + (kk0 + kk) * 128 + o_base);
                ulonglong2 w0 = wp[0], w1 = wp[1];
#pragma unroll
                for (int i = 0; i < 4; ++i) {
                    float x = reinterpret_cast<const float*>(&xr[i])[kk];
                    ull av = pack_dup(x);
                    ffma2(acc[i][0], av, w0.x);
                    ffma2(acc[i][1], av, w0.y);
                    ffma2(acc[i][2], av, w1.x);
                    ffma2(acc[i][3], av, w1.y);
                }
            }
        }

        if (c + 1 < NCHUNK) sts_chunk((c + 1) & 1);
        __syncthreads();
    }

    // ---- epilogue: unpack, +bias, float4 stores ----
#pragma unroll
    for (int i = 0; i < 4; ++i) {
        int e = e0 + e_base + i;
        if (e >= E) continue;
        float f[8];
#pragma unroll
        for (int j = 0; j < 4; ++j) unpack2(acc[i][j], f[2 * j], f[2 * j + 1]);
        float4 v0 = make_float4(f[0] + bb[0], f[1] + bb[1], f[2] + bb[2], f[3] + bb[3]);
        float4 v1 = make_float4(f[4] + bb[4], f[5] + bb[5], f[6] + bb[6], f[7] + bb[7]);
        float* op = out + (size_t)e * 128 + o_base;
        *reinterpret_cast<float4*>(op)     = v0;
        *reinterpret_cast<float4*>(op + 4) = v1;
    }
}

extern "C" void kernel_launch(void* const* d_in, const int* in_sizes, int n_in,
                              void* d_out, int out_size)
{
    const float* nodes = (const float*)d_in[0];
    const float* edges = (const float*)d_in[1];
    const int*   recv  = (const int*)d_in[2];
    const int*   send  = (const int*)d_in[3];
    const float* W     = (const float*)d_in[4];
    const float* bias  = (const float*)d_in[5];
    float*       out   = (float*)d_out;
    int E = in_sizes[2];

    cudaFuncSetAttribute(edgeblock_kernel,
                         cudaFuncAttributeMaxDynamicSharedMemorySize, SM_TOTAL);

    prep_W_kernel<<<(NCHUNK * KC * 128 + 255) / 256, 256>>>(W);
    int grid = (E + TE - 1) / TE;
    edgeblock_kernel<<<grid, THREADS, SM_TOTAL>>>(nodes, edges, recv, send, bias, out, E);
}

// round 6
// speedup vs baseline: 2.7569x; 2.7569x over previous
#include <cuda_runtime.h>
#include <cuda_bf16.h>
#include <cstdint>

// EdgeBlock: out[e,:] = W @ concat(edges[e], nodes[recv[e]], nodes[send[e]]) + b
// E=500000, NODE_D=EDGE_D=128, IN_D=384, W [128,384] row-major, out [E,128] f32.
// Legacy tensor path: mma.sync m16n8k16 bf16 (compute_103-legal) with hi/lo
// split for fp32-level accuracy: x*w ~= xh*wh + xh*wl + xl*wh.

#define IN_D    384
#define OUT_D   128
#define TM      128
#define KC      64
#define NCHUNK  6
#define THREADS 256
#define STR     72              // bf16 per smem row (64 + 8 pad) -> 144 B

// smem byte offsets
#define XHI_OFF   0
#define XLO_OFF   18432
#define WHI_OFF   36864
#define WLO_OFF   55296
#define BIAS_OFF  73728
#define RIDX_OFF  74240
#define SIDX_OFF  74752
#define SM_TOTAL  75264

__device__ __forceinline__ uint32_t smem_u32(const void* p) {
    uint32_t a;
    asm("{ .reg .u64 t; cvta.to.shared.u64 t, %1; cvt.u32.u64 %0, t; }" : "=r"(a) : "l"(p));
    return a;
}
__device__ __forceinline__ void ldsm_x4(uint32_t& r0, uint32_t& r1, uint32_t& r2, uint32_t& r3,
                                        uint32_t addr) {
    asm volatile("ldmatrix.sync.aligned.m8n8.x4.shared.b16 {%0,%1,%2,%3}, [%4];"
                 : "=r"(r0), "=r"(r1), "=r"(r2), "=r"(r3) : "r"(addr));
}
__device__ __forceinline__ void mma16816(float& c0, float& c1, float& c2, float& c3,
                                         uint32_t a0, uint32_t a1, uint32_t a2, uint32_t a3,
                                         uint32_t b0, uint32_t b1) {
    asm volatile("mma.sync.aligned.m16n8k16.row.col.f32.bf16.bf16.f32 "
                 "{%0,%1,%2,%3}, {%4,%5,%6,%7}, {%8,%9}, {%0,%1,%2,%3};"
                 : "+f"(c0), "+f"(c1), "+f"(c2), "+f"(c3)
                 : "r"(a0), "r"(a1), "r"(a2), "r"(a3), "r"(b0), "r"(b1));
}

// ---- W pre-split into bf16 hi/lo, plain [n][384] layout ----
__device__ __align__(16) __nv_bfloat16 g_Whi[OUT_D * IN_D];
__device__ __align__(16) __nv_bfloat16 g_Wlo[OUT_D * IN_D];

__global__ void prep_W_kernel(const float* __restrict__ W) {
    int i = blockIdx.x * blockDim.x + threadIdx.x;
    if (i >= OUT_D * IN_D) return;
    float w = W[i];
    __nv_bfloat16 hi = __float2bfloat16(w);
    g_Whi[i] = hi;
    g_Wlo[i] = __float2bfloat16(w - __bfloat162float(hi));
}

__global__ void __launch_bounds__(THREADS, 2)
edgeblock_mma_kernel(const float* __restrict__ nodes,
                     const float* __restrict__ edges,
                     const int* __restrict__ recv,
                     const int* __restrict__ send,
                     const float* __restrict__ bias,
                     float* __restrict__ out,
                     int E)
{
    extern __shared__ char smem[];
    const uint32_t sm = smem_u32(smem);
    const int t = threadIdx.x;
    const int lane = t & 31, wid = t >> 5;
    const int e0 = blockIdx.x * TM;

    // warp tiling: 2 (m) x 4 (n)
    const int m_base = (wid & 1) * 64;
    const int n_base = (wid >> 1) * 32;

    int* Ridx = (int*)(smem + RIDX_OFF);
    int* Sidx = (int*)(smem + SIDX_OFF);
    float* Bs = (float*)(smem + BIAS_OFF);
    if (t < TM) {
        int e = e0 + t;
        Ridx[t] = (e < E) ? recv[e] : 0;
        Sidx[t] = (e < E) ? send[e] : 0;
        Bs[t] = bias[t];
    }
    __syncthreads();

    // ldmatrix per-lane address components
    const int lr = lane & 7, g4 = lane >> 3;
    // A: g0 rows0-7@k, g1 rows8-15@k, g2 rows0-7@k+8, g3 rows8-15@k+8
    const uint32_t a_off = (uint32_t)(m_base + lr + (g4 & 1) * 8) * (STR * 2) + (g4 >> 1) * 16;
    // B: g0 n0-7@k, g1 n0-7@k+8, g2 n8-15@k, g3 n8-15@k+8
    const uint32_t b_off = (uint32_t)(n_base + lr + (g4 >> 1) * 8) * (STR * 2) + (g4 & 1) * 16;

    float acc[4][4][4];
#pragma unroll
    for (int i = 0; i < 4; ++i)
#pragma unroll
        for (int j = 0; j < 4; ++j)
#pragma unroll
            for (int k = 0; k < 4; ++k) acc[i][j][k] = 0.f;

    // staging roles
    const int sr = t >> 1;          // X row 0..127
    const int sh = t & 1;           // 32-col half of the 64-col chunk
    const int wr = t >> 1;          // W row, same mapping

    for (int c = 0; c < NCHUNK; ++c) {
        const int xoff = (c & 1) * KC;   // offset within 128-wide source block
        const int woff = c * KC;         // offset within 384-wide W  (R5 BUG FIX)
        // ---- stage X: gather + fp32->bf16 hi/lo split ----
        {
            const float* src;
            int e = e0 + sr;
            if (c < 2)      src = (e < E) ? edges + (size_t)e * 128 + xoff : nullptr;
            else if (c < 4) src = nodes + (size_t)Ridx[sr] * 128 + xoff;
            else            src = nodes + (size_t)Sidx[sr] * 128 + xoff;
#pragma unroll
            for (int q = 0; q < 4; ++q) {
                int col0 = sh * 32 + q * 8;
                float4 fa = make_float4(0.f, 0.f, 0.f, 0.f), fb = fa;
                if (src) {
                    fa = *reinterpret_cast<const float4*>(src + col0);
                    fb = *reinterpret_cast<const float4*>(src + col0 + 4);
                }
                const float f[8] = {fa.x, fa.y, fa.z, fa.w, fb.x, fb.y, fb.z, fb.w};
                __nv_bfloat16 hi[8], lo[8];
#pragma unroll
                for (int j = 0; j < 8; ++j) {
                    hi[j] = __float2bfloat16(f[j]);
                    lo[j] = __float2bfloat16(f[j] - __bfloat162float(hi[j]));
                }
                uint32_t doff = (uint32_t)sr * (STR * 2) + col0 * 2;
                *reinterpret_cast<uint4*>(smem + XHI_OFF + doff) = *reinterpret_cast<uint4*>(hi);
                *reinterpret_cast<uint4*>(smem + XLO_OFF + doff) = *reinterpret_cast<uint4*>(lo);
            }
        }
        // ---- stage W: copy pre-split chunks (coalesced 16B) ----
        {
            const uint4* ghi = reinterpret_cast<const uint4*>(g_Whi + wr * IN_D + woff + sh * 32);
            const uint4* glo = reinterpret_cast<const uint4*>(g_Wlo + wr * IN_D + woff + sh * 32);
            uint32_t doff = (uint32_t)wr * (STR * 2) + sh * 64;
#pragma unroll
            for (int q = 0; q < 4; ++q) {
                *reinterpret_cast<uint4*>(smem + WHI_OFF + doff + q * 16) = ghi[q];
                *reinterpret_cast<uint4*>(smem + WLO_OFF + doff + q * 16) = glo[q];
            }
        }
        __syncthreads();

        // ---- compute: 4 k16 steps, 3 passes each ----
#pragma unroll
        for (int k16 = 0; k16 < KC; k16 += 16) {
            uint32_t a[4][4], bh[4][2], bl[4][2];
            // B frags: 2 x ldsm.x4 covers 4 n8-tiles per buffer
#pragma unroll
            for (int np = 0; np < 2; ++np) {
                uint32_t addr = sm + WHI_OFF + b_off + np * 16 * (STR * 2) + k16 * 2;
                ldsm_x4(bh[np * 2][0], bh[np * 2][1], bh[np * 2 + 1][0], bh[np * 2 + 1][1], addr);
                addr = sm + WLO_OFF + b_off + np * 16 * (STR * 2) + k16 * 2;
                ldsm_x4(bl[np * 2][0], bl[np * 2][1], bl[np * 2 + 1][0], bl[np * 2 + 1][1], addr);
            }
            // A hi frags
#pragma unroll
            for (int tm = 0; tm < 4; ++tm) {
                uint32_t addr = sm + XHI_OFF + a_off + tm * 16 * (STR * 2) + k16 * 2;
                ldsm_x4(a[tm][0], a[tm][1], a[tm][2], a[tm][3], addr);
            }
            // pass 1: Ahi x Whi ; pass 2: Ahi x Wlo
#pragma unroll
            for (int tm = 0; tm < 4; ++tm)
#pragma unroll
                for (int tn = 0; tn < 4; ++tn) {
                    mma16816(acc[tm][tn][0], acc[tm][tn][1], acc[tm][tn][2], acc[tm][tn][3],
                             a[tm][0], a[tm][1], a[tm][2], a[tm][3], bh[tn][0], bh[tn][1]);
                    mma16816(acc[tm][tn][0], acc[tm][tn][1], acc[tm][tn][2], acc[tm][tn][3],
                             a[tm][0], a[tm][1], a[tm][2], a[tm][3], bl[tn][0], bl[tn][1]);
                }
            // A lo frags (reuse regs), pass 3: Alo x Whi
#pragma unroll
            for (int tm = 0; tm < 4; ++tm) {
                uint32_t addr = sm + XLO_OFF + a_off + tm * 16 * (STR * 2) + k16 * 2;
                ldsm_x4(a[tm][0], a[tm][1], a[tm][2], a[tm][3], addr);
            }
#pragma unroll
            for (int tm = 0; tm < 4; ++tm)
#pragma unroll
                for (int tn = 0; tn < 4; ++tn)
                    mma16816(acc[tm][tn][0], acc[tm][tn][1], acc[tm][tn][2], acc[tm][tn][3],
                             a[tm][0], a[tm][1], a[tm][2], a[tm][3], bh[tn][0], bh[tn][1]);
        }
        __syncthreads();
    }

    // ---- epilogue: frag layout -> global, + bias ----
    const int gq = lane >> 2, t4 = lane & 3;
#pragma unroll
    for (int tm = 0; tm < 4; ++tm) {
        int r0 = e0 + m_base + tm * 16 + gq;
        int r1 = r0 + 8;
#pragma unroll
        for (int tn = 0; tn < 4; ++tn) {
            int cbase = n_base + tn * 8 + t4 * 2;
            float b0 = Bs[cbase], b1 = Bs[cbase + 1];
            if (r0 < E) {
                float2 v = make_float2(acc[tm][tn][0] + b0, acc[tm][tn][1] + b1);
                *reinterpret_cast<float2*>(out + (size_t)r0 * OUT_D + cbase) = v;
            }
            if (r1 < E) {
                float2 v = make_float2(acc[tm][tn][2] + b0, acc[tm][tn][3] + b1);
                *reinterpret_cast<float2*>(out + (size_t)r1 * OUT_D + cbase) = v;
            }
        }
    }
}

extern "C" void kernel_launch(void* const* d_in, const int* in_sizes, int n_in,
                              void* d_out, int out_size)
{
    const float* nodes = (const float*)d_in[0];
    const float* edges = (const float*)d_in[1];
    const int*   recv  = (const int*)d_in[2];
    const int*   send  = (const int*)d_in[3];
    const float* W     = (const float*)d_in[4];
    const float* bias  = (const float*)d_in[5];
    float*       out   = (float*)d_out;
    int E = in_sizes[2];

    cudaFuncSetAttribute(edgeblock_mma_kernel,
                         cudaFuncAttributeMaxDynamicSharedMemorySize, SM_TOTAL);

    prep_W_kernel<<<(OUT_D * IN_D + 255) / 256, 256>>>(W);
    int grid = (E + TM - 1) / TM;
    edgeblock_mma_kernel<<<grid, THREADS, SM_TOTAL>>>(nodes, edges, recv, send, bias, out, E);
}

// round 7
// speedup vs baseline: 2.8837x; 1.0460x over previous
#include <cuda_runtime.h>
#include <cuda_bf16.h>
#include <cstdint>

// EdgeBlock: out[e,:] = W @ concat(edges[e], nodes[recv[e]], nodes[send[e]]) + b
// E=500000, NODE_D=EDGE_D=128, IN_D=384, W [128,384] row-major, out [E,128] f32.
// mma.sync m16n8k16 bf16, 3-pass hi/lo split (validated rel_err ~5e-6 in R6).
// R7: double-buffered smem + register-pipelined staging, 1 CTA/SM, 1 sync/chunk.

#define IN_D    384
#define OUT_D   128
#define TM      128
#define KC      64
#define NCHUNK  6
#define THREADS 256
#define STR2    144            // bytes per smem tile row (64 bf16 + 8 pad)

// smem byte offsets: two buffers of (XHI,XLO,WHI,WLO), 73728 each
#define XHI(b)   ((b) * 73728)
#define XLO(b)   ((b) * 73728 + 18432)
#define WHI(b)   ((b) * 73728 + 36864)
#define WLO(b)   ((b) * 73728 + 55296)
#define BIAS_OFF 147456
#define SM_TOTAL 147968

__device__ __forceinline__ uint32_t smem_u32(const void* p) {
    uint32_t a;
    asm("{ .reg .u64 t; cvta.to.shared.u64 t, %1; cvt.u32.u64 %0, t; }" : "=r"(a) : "l"(p));
    return a;
}
__device__ __forceinline__ void ldsm_x4(uint32_t& r0, uint32_t& r1, uint32_t& r2, uint32_t& r3,
                                        uint32_t addr) {
    asm volatile("ldmatrix.sync.aligned.m8n8.x4.shared.b16 {%0,%1,%2,%3}, [%4];"
                 : "=r"(r0), "=r"(r1), "=r"(r2), "=r"(r3) : "r"(addr));
}
__device__ __forceinline__ void mma16816(float& c0, float& c1, float& c2, float& c3,
                                         uint32_t a0, uint32_t a1, uint32_t a2, uint32_t a3,
                                         uint32_t b0, uint32_t b1) {
    asm volatile("mma.sync.aligned.m16n8k16.row.col.f32.bf16.bf16.f32 "
                 "{%0,%1,%2,%3}, {%4,%5,%6,%7}, {%8,%9}, {%0,%1,%2,%3};"
                 : "+f"(c0), "+f"(c1), "+f"(c2), "+f"(c3)
                 : "r"(a0), "r"(a1), "r"(a2), "r"(a3), "r"(b0), "r"(b1));
}

// ---- W pre-split into bf16 hi/lo, plain [n][384] row-major ----
__device__ __align__(16) __nv_bfloat16 g_Whi[OUT_D * IN_D];
__device__ __align__(16) __nv_bfloat16 g_Wlo[OUT_D * IN_D];

__global__ void prep_W_kernel(const float* __restrict__ W) {
    int i = blockIdx.x * blockDim.x + threadIdx.x;
    if (i >= OUT_D * IN_D) return;
    float w = W[i];
    __nv_bfloat16 hi = __float2bfloat16(w);
    g_Whi[i] = hi;
    g_Wlo[i] = __float2bfloat16(w - __bfloat162float(hi));
}

__global__ void __launch_bounds__(THREADS, 1)
edgeblock_mma_kernel(const float* __restrict__ nodes,
                     const float* __restrict__ edges,
                     const int* __restrict__ recv,
                     const int* __restrict__ send,
                     const float* __restrict__ bias,
                     float* __restrict__ out,
                     int E)
{
    extern __shared__ char smem[];
    const uint32_t sm = smem_u32(smem);
    const int t = threadIdx.x;
    const int lane = t & 31, wid = t >> 5;
    const int e0 = blockIdx.x * TM;

    // warp tiling: 2 (m) x 4 (n)
    const int m_base = (wid & 1) * 64;
    const int n_base = (wid >> 1) * 32;

    float* Bs = (float*)(smem + BIAS_OFF);
    if (t < OUT_D) Bs[t] = bias[t];

    // per-thread staging role: 2 threads per tile row
    const int sr = t >> 1;          // row 0..127
    const int sh = t & 1;           // 32-float half of the 64-col chunk
    const int e_row = e0 + sr;
    const bool e_ok = e_row < E;
    const int ridx = e_ok ? recv[e_row] : 0;
    const int sidx = e_ok ? send[e_row] : 0;
    const float* xsrc0 = e_ok ? edges + (size_t)e_row * 128 : nullptr;
    const float* xsrc1 = nodes + (size_t)ridx * 128;
    const float* xsrc2 = nodes + (size_t)sidx * 128;

    // ldmatrix per-lane address components (validated in R6)
    const int lr = lane & 7, g4 = lane >> 3;
    const uint32_t a_off = (uint32_t)(m_base + lr + (g4 & 1) * 8) * STR2 + (g4 >> 1) * 16;
    const uint32_t b_off = (uint32_t)(n_base + lr + (g4 >> 1) * 8) * STR2 + (g4 & 1) * 16;

    float acc[4][4][4];
#pragma unroll
    for (int i = 0; i < 4; ++i)
#pragma unroll
        for (int j = 0; j < 4; ++j)
#pragma unroll
            for (int k = 0; k < 4; ++k) acc[i][j][k] = 0.f;

    // staging registers (held across compute for pipelining)
    float4 xreg[8];                  // 128 B of X row
    uint4  wh_reg[4], wl_reg[4];     // 64 B each of W row (hi/lo)

    // ---- LDG for chunk c into regs ----
    auto ldg_stage = [&](int c) {
        const int xoff = (c & 1) * KC;
        const float* s = (c < 2) ? xsrc0 : (c < 4) ? xsrc1 : xsrc2;
        if (s) {
            const float4* p = reinterpret_cast<const float4*>(s + xoff + sh * 32);
#pragma unroll
            for (int i = 0; i < 8; ++i) xreg[i] = p[i];
        }
        const uint4* ph = reinterpret_cast<const uint4*>(g_Whi + (size_t)sr * IN_D + c * KC + sh * 32);
        const uint4* pl = reinterpret_cast<const uint4*>(g_Wlo + (size_t)sr * IN_D + c * KC + sh * 32);
#pragma unroll
        for (int i = 0; i < 4; ++i) { wh_reg[i] = ph[i]; wl_reg[i] = pl[i]; }
    };

    // ---- convert + STS regs into buffer b ----
    auto sts_stage = [&](int b) {
        const uint32_t rbase = (uint32_t)sr * STR2 + sh * 64;
#pragma unroll
        for (int i = 0; i < 4; ++i) {
            const float f[8] = {xreg[2*i].x, xreg[2*i].y, xreg[2*i].z, xreg[2*i].w,
                                xreg[2*i+1].x, xreg[2*i+1].y, xreg[2*i+1].z, xreg[2*i+1].w};
            __nv_bfloat16 hi[8], lo[8];
#pragma unroll
            for (int j = 0; j < 8; ++j) {
                hi[j] = __float2bfloat16(f[j]);
                lo[j] = __float2bfloat16(f[j] - __bfloat162float(hi[j]));
            }
            *reinterpret_cast<uint4*>(smem + XHI(b) + rbase + i * 16) = *reinterpret_cast<uint4*>(hi);
            *reinterpret_cast<uint4*>(smem + XLO(b) + rbase + i * 16) = *reinterpret_cast<uint4*>(lo);
        }
#pragma unroll
        for (int i = 0; i < 4; ++i) {
            *reinterpret_cast<uint4*>(smem + WHI(b) + rbase + i * 16) = wh_reg[i];
            *reinterpret_cast<uint4*>(smem + WLO(b) + rbase + i * 16) = wl_reg[i];
        }
    };

    // ---- compute chunk from buffer b ----
    auto compute = [&](int b) {
#pragma unroll
        for (int k16 = 0; k16 < KC; k16 += 16) {
            const uint32_t koff = k16 * 2;
            uint32_t a[4][4], bh[4][2], bl[4][2];
#pragma unroll
            for (int np = 0; np < 2; ++np) {
                uint32_t addr = sm + WHI(b) + b_off + np * 16 * STR2 + koff;
                ldsm_x4(bh[np*2][0], bh[np*2][1], bh[np*2+1][0], bh[np*2+1][1], addr);
                addr = sm + WLO(b) + b_off + np * 16 * STR2 + koff;
                ldsm_x4(bl[np*2][0], bl[np*2][1], bl[np*2+1][0], bl[np*2+1][1], addr);
            }
#pragma unroll
            for (int tm = 0; tm < 4; ++tm) {
                uint32_t addr = sm + XHI(b) + a_off + tm * 16 * STR2 + koff;
                ldsm_x4(a[tm][0], a[tm][1], a[tm][2], a[tm][3], addr);
            }
#pragma unroll
            for (int tm = 0; tm < 4; ++tm)
#pragma unroll
                for (int tn = 0; tn < 4; ++tn) {
                    mma16816(acc[tm][tn][0], acc[tm][tn][1], acc[tm][tn][2], acc[tm][tn][3],
                             a[tm][0], a[tm][1], a[tm][2], a[tm][3], bh[tn][0], bh[tn][1]);
                    mma16816(acc[tm][tn][0], acc[tm][tn][1], acc[tm][tn][2], acc[tm][tn][3],
                             a[tm][0], a[tm][1], a[tm][2], a[tm][3], bl[tn][0], bl[tn][1]);
                }
#pragma unroll
            for (int tm = 0; tm < 4; ++tm) {
                uint32_t addr = sm + XLO(b) + a_off + tm * 16 * STR2 + koff;
                ldsm_x4(a[tm][0], a[tm][1], a[tm][2], a[tm][3], addr);
            }
#pragma unroll
            for (int tm = 0; tm < 4; ++tm)
#pragma unroll
                for (int tn = 0; tn < 4; ++tn)
                    mma16816(acc[tm][tn][0], acc[tm][tn][1], acc[tm][tn][2], acc[tm][tn][3],
                             a[tm][0], a[tm][1], a[tm][2], a[tm][3], bh[tn][0], bh[tn][1]);
        }
    };

    // ---- software pipeline: 1 sync per chunk ----
    ldg_stage(0);
    sts_stage(0);
    __syncthreads();
    for (int c = 0; c < NCHUNK; ++c) {
        if (c + 1 < NCHUNK) ldg_stage(c + 1);     // long-latency LDG overlaps MMA
        compute(c & 1);
        if (c + 1 < NCHUNK) sts_stage((c + 1) & 1);
        __syncthreads();
    }

    // ---- epilogue: frag layout -> global, + bias ----
    const int gq = lane >> 2, t4 = lane & 3;
#pragma unroll
    for (int tm = 0; tm < 4; ++tm) {
        int r0 = e0 + m_base + tm * 16 + gq;
        int r1 = r0 + 8;
#pragma unroll
        for (int tn = 0; tn < 4; ++tn) {
            int cbase = n_base + tn * 8 + t4 * 2;
            float b0 = Bs[cbase], b1 = Bs[cbase + 1];
            if (r0 < E) {
                float2 v = make_float2(acc[tm][tn][0] + b0, acc[tm][tn][1] + b1);
                *reinterpret_cast<float2*>(out + (size_t)r0 * OUT_D + cbase) = v;
            }
            if (r1 < E) {
                float2 v = make_float2(acc[tm][tn][2] + b0, acc[tm][tn][3] + b1);
                *reinterpret_cast<float2*>(out + (size_t)r1 * OUT_D + cbase) = v;
            }
        }
    }
}

extern "C" void kernel_launch(void* const* d_in, const int* in_sizes, int n_in,
                              void* d_out, int out_size)
{
    const float* nodes = (const float*)d_in[0];
    const float* edges = (const float*)d_in[1];
    const int*   recv  = (const int*)d_in[2];
    const int*   send  = (const int*)d_in[3];
    const float* W     = (const float*)d_in[4];
    const float* bias  = (const float*)d_in[5];
    float*       out   = (float*)d_out;
    int E = in_sizes[2];

    cudaFuncSetAttribute(edgeblock_mma_kernel,
                         cudaFuncAttributeMaxDynamicSharedMemorySize, SM_TOTAL);

    prep_W_kernel<<<(OUT_D * IN_D + 255) / 256, 256>>>(W);
    int grid = (E + TM - 1) / TM;
    edgeblock_mma_kernel<<<grid, THREADS, SM_TOTAL>>>(nodes, edges, recv, send, bias, out, E);
}